// round 1
// baseline (speedup 1.0000x reference)
#include <cuda_runtime.h>
#include <math.h>

#define BATCH 4
#define SEQ 8192
#define DIMN 1024
#define CHUNK 16
#define NCHUNK (SEQ / CHUNK)              /* 512 */
#define NWARP_TOTAL (BATCH * NCHUNK)      /* 2048 */
#define WARPS_PER_BLOCK 8
#define NBLOCKS (NWARP_TOTAL / WARPS_PER_BLOCK) /* 256 */
#define LN_EPS_F 1e-5f

// Scratch: chunk-final local states and chunk-entry carries. [b][chunk][1024]
__device__ float g_S[NWARP_TOTAL * DIMN];
__device__ float g_P[NWARP_TOTAL * DIMN];

__device__ __forceinline__ void head_params(const float* __restrict__ alphas,
                                            float* a_i, float* om_i) {
#pragma unroll
    for (int i = 0; i < 8; i++) {
        float al = __ldg(alphas + i);
        float a = 1.0f / (1.0f + expf(-al));
        a_i[i] = a;
        om_i[i] = 1.0f - a;
    }
}

// Fused LayerNorm + per-chunk EMA scan. One warp owns one chunk of 16 rows,
// all 1024 channels (lane covers channels i*128 + lane*4 .. +3, i = head).
// WRITE_OUT=false: local scan from zero state, emit chunk-final state to g_S.
// WRITE_OUT=true : scan seeded from g_P carry, emit out = y + u*D.
template <bool WRITE_OUT>
__global__ __launch_bounds__(256, 2) void mhesa_scan(
    const float* __restrict__ x, const float* __restrict__ gamma,
    const float* __restrict__ beta, const float* __restrict__ alphas,
    const float* __restrict__ paramD, float* __restrict__ out)
{
    int warp = blockIdx.x * WARPS_PER_BLOCK + (threadIdx.x >> 5);
    if (WRITE_OUT) warp = NWARP_TOTAL - 1 - warp;  // reverse order: reuse K1's L2 tail
    const int lane = threadIdx.x & 31;
    const int b = warp >> 9;              // / NCHUNK
    const int c = warp & (NCHUNK - 1);

    float a_i[8], om_i[8];
    head_params(alphas, a_i, om_i);

    float4 y[8];
    if (WRITE_OUT) {
        const float* p = g_P + (size_t)warp * DIMN + lane * 4;
#pragma unroll
        for (int i = 0; i < 8; i++) y[i] = *(const float4*)(p + i * 128);
    } else {
#pragma unroll
        for (int i = 0; i < 8; i++) y[i] = make_float4(0.f, 0.f, 0.f, 0.f);
    }

    const size_t row0 = ((size_t)b * SEQ + (size_t)c * CHUNK) * DIMN;
    const float* xp = x + row0 + lane * 4;
    float* op = out + row0 + lane * 4;

    for (int r = 0; r < CHUNK; r++) {
        float4 xv[8];
        float sum = 0.f, sq = 0.f;
#pragma unroll
        for (int i = 0; i < 8; i++) {
            xv[i] = __ldcs((const float4*)(xp + i * 128));  // streaming: keep L1 for params
            sum += (xv[i].x + xv[i].y) + (xv[i].z + xv[i].w);
            sq = fmaf(xv[i].x, xv[i].x, sq);
            sq = fmaf(xv[i].y, xv[i].y, sq);
            sq = fmaf(xv[i].z, xv[i].z, sq);
            sq = fmaf(xv[i].w, xv[i].w, sq);
        }
#pragma unroll
        for (int off = 16; off; off >>= 1) {
            sum += __shfl_xor_sync(0xffffffffu, sum, off);
            sq  += __shfl_xor_sync(0xffffffffu, sq,  off);
        }
        const float mean = sum * (1.0f / (float)DIMN);
        const float var  = fmaf(sq, 1.0f / (float)DIMN, -mean * mean);
        const float inv  = rsqrtf(var + LN_EPS_F);
        const float nm   = -mean * inv;

#pragma unroll
        for (int i = 0; i < 8; i++) {
            const int co = i * 128 + lane * 4;
            const float4 g  = __ldg((const float4*)(gamma + co));
            const float4 be = __ldg((const float4*)(beta + co));
            float4 u;
            u.x = fmaf(fmaf(xv[i].x, inv, nm), g.x, be.x);
            u.y = fmaf(fmaf(xv[i].y, inv, nm), g.y, be.y);
            u.z = fmaf(fmaf(xv[i].z, inv, nm), g.z, be.z);
            u.w = fmaf(fmaf(xv[i].w, inv, nm), g.w, be.w);
            const float ai = a_i[i], oi = om_i[i];
            y[i].x = fmaf(oi, y[i].x, ai * u.x);
            y[i].y = fmaf(oi, y[i].y, ai * u.y);
            y[i].z = fmaf(oi, y[i].z, ai * u.z);
            y[i].w = fmaf(oi, y[i].w, ai * u.w);
            if (WRITE_OUT) {
                const float4 d = __ldg((const float4*)(paramD + co));
                float4 o;
                o.x = fmaf(u.x, d.x, y[i].x);
                o.y = fmaf(u.y, d.y, y[i].y);
                o.z = fmaf(u.z, d.z, y[i].z);
                o.w = fmaf(u.w, d.w, y[i].w);
                __stcs((float4*)(op + i * 128), o);
            }
        }
        xp += DIMN;
        if (WRITE_OUT) op += DIMN;
    }

    if (!WRITE_OUT) {
        float* s = g_S + (size_t)warp * DIMN + lane * 4;
#pragma unroll
        for (int i = 0; i < 8; i++) *(float4*)(s + i * 128) = y[i];
    }
}

// Inter-chunk carry scan: P[b,0]=0 ; P[b,c] = om^CHUNK * P[b,c-1] + S[b,c-1].
// One thread per (b, channel); loads are independent of the FMA chain so they pipeline.
__global__ void mhesa_carry(const float* __restrict__ alphas)
{
    const int t  = blockIdx.x * blockDim.x + threadIdx.x;  // 0..4095
    const int b  = t >> 10;
    const int ch = t & (DIMN - 1);
    const float al = __ldg(alphas + (ch >> 7));
    const float a  = 1.0f / (1.0f + expf(-al));
    const float om = 1.0f - a;
    const float om2 = om * om;
    const float om4 = om2 * om2;
    const float om8 = om4 * om4;
    const float omC = om8 * om8;  // om^16 == om^CHUNK
    float p = 0.f;
    const size_t base = (size_t)b * NCHUNK * DIMN + ch;
#pragma unroll 4
    for (int c = 0; c < NCHUNK; c++) {
        const size_t idx = base + (size_t)c * DIMN;
        g_P[idx] = p;
        p = fmaf(omC, p, g_S[idx]);
    }
}

extern "C" void kernel_launch(void* const* d_in, const int* in_sizes, int n_in,
                              void* d_out, int out_size)
{
    const float* x      = (const float*)d_in[0];
    const float* gamma  = (const float*)d_in[1];
    const float* beta   = (const float*)d_in[2];
    const float* alphas = (const float*)d_in[3];
    const float* paramD = (const float*)d_in[4];
    float* out = (float*)d_out;

    mhesa_scan<false><<<NBLOCKS, 256>>>(x, gamma, beta, alphas, paramD, out);
    mhesa_carry<<<(BATCH * DIMN) / 256, 256>>>(alphas);
    mhesa_scan<true><<<NBLOCKS, 256>>>(x, gamma, beta, alphas, paramD, out);
}

// round 3
// speedup vs baseline: 1.4658x; 1.4658x over previous
#include <cuda_runtime.h>
#include <math.h>

#define BATCH 4
#define SEQ 8192
#define DIMN 1024
#define CHUNK 8
#define NCHUNK (SEQ / CHUNK)              /* 1024 */
#define NWARP_TOTAL (BATCH * NCHUNK)      /* 4096 */
#define WARPS_PER_BLOCK 8
#define NBLOCKS (NWARP_TOTAL / WARPS_PER_BLOCK) /* 512 */
#define NSEG 16
#define SEGLEN (NCHUNK / NSEG)            /* 64 */
#define LN_EPS_F 1e-5f

// Scratch (z-space chunk states / entry carries / segment aggregates)
__device__ float g_S[NWARP_TOTAL * DIMN];           // 16 MB
__device__ float g_P[NWARP_TOTAL * DIMN];           // 16 MB
__device__ float g_A[BATCH * NSEG * DIMN];          // 256 KB

// Forced 128-bit global load: guarantees a real (re)load, defeats CSE/hoisting
// so register pressure stays under the 3-blocks/SM cap. Hits L1 (loaded moments ago).
__device__ __forceinline__ float4 ldg_f4_force(const float* p) {
    float4 v;
    asm volatile("ld.global.nc.v4.f32 {%0,%1,%2,%3}, [%4];"
                 : "=f"(v.x), "=f"(v.y), "=f"(v.z), "=f"(v.w) : "l"(p));
    return v;
}

// Fused LayerNorm + per-chunk EMA scan in z-space (z = y / a, z' = om*z + u).
// One warp owns one chunk of CHUNK rows, all 1024 channels
// (lane covers channels i*128 + lane*4 .. +3; i = head index).
template <bool WRITE_OUT>
__global__ __launch_bounds__(256, 3) void mhesa_scan(
    const float* __restrict__ x, const float* __restrict__ gamma,
    const float* __restrict__ beta, const float* __restrict__ alphas,
    const float* __restrict__ paramD, float* __restrict__ out)
{
    int warp = blockIdx.x * WARPS_PER_BLOCK + (threadIdx.x >> 5);
    if (WRITE_OUT) warp = NWARP_TOTAL - 1 - warp;  // reverse: reuse K1's L2 tail
    const int lane = threadIdx.x & 31;
    const int b = warp >> 10;             // / NCHUNK
    const int c = warp & (NCHUNK - 1);

    float om_i[8];
#pragma unroll
    for (int i = 0; i < 8; i++) {
        float al = __ldg(alphas + i);
        om_i[i] = 1.0f - 1.0f / (1.0f + expf(-al));   // om = 1 - sigmoid(alpha)
    }

    float4 z[8];
    if (WRITE_OUT) {
        const float* p = g_P + (size_t)warp * DIMN + lane * 4;
#pragma unroll
        for (int i = 0; i < 8; i++) z[i] = *(const float4*)(p + i * 128);
    } else {
#pragma unroll
        for (int i = 0; i < 8; i++) z[i] = make_float4(0.f, 0.f, 0.f, 0.f);
    }

    const size_t row0 = ((size_t)b * SEQ + (size_t)c * CHUNK) * DIMN;
    const float* xp = x + row0 + lane * 4;
    float* op = out + row0 + lane * 4;

    for (int r = 0; r < CHUNK; r++) {
        // Phase 1: load row once, accumulate LN moments (xv dies immediately).
        float sum = 0.f, sq = 0.f;
#pragma unroll
        for (int i = 0; i < 8; i++) {
            float4 v = __ldg((const float4*)(xp + i * 128));
            sum += (v.x + v.y) + (v.z + v.w);
            sq = fmaf(v.x, v.x, sq);
            sq = fmaf(v.y, v.y, sq);
            sq = fmaf(v.z, v.z, sq);
            sq = fmaf(v.w, v.w, sq);
        }
#pragma unroll
        for (int off = 16; off; off >>= 1) {
            sum += __shfl_xor_sync(0xffffffffu, sum, off);
            sq  += __shfl_xor_sync(0xffffffffu, sq,  off);
        }
        const float mean = sum * (1.0f / (float)DIMN);
        const float var  = fmaf(sq, 1.0f / (float)DIMN, -mean * mean);
        const float inv  = rsqrtf(var + LN_EPS_F);
        const float nm   = -mean * inv;

        // Phase 2: re-load x (same address as phase 1 -> L1 hit) + params,
        // normalize, scan.
#pragma unroll
        for (int i = 0; i < 8; i++) {
            const int co = i * 128 + lane * 4;   // channel offset (for params)
            const float4 v  = ldg_f4_force(xp + i * 128);   // xp already has lane*4
            const float4 g  = ldg_f4_force(gamma + co);
            const float4 be = ldg_f4_force(beta + co);
            float4 u;
            u.x = fmaf(fmaf(v.x, inv, nm), g.x, be.x);
            u.y = fmaf(fmaf(v.y, inv, nm), g.y, be.y);
            u.z = fmaf(fmaf(v.z, inv, nm), g.z, be.z);
            u.w = fmaf(fmaf(v.w, inv, nm), g.w, be.w);
            const float om = om_i[i];
            z[i].x = fmaf(om, z[i].x, u.x);
            z[i].y = fmaf(om, z[i].y, u.y);
            z[i].z = fmaf(om, z[i].z, u.z);
            z[i].w = fmaf(om, z[i].w, u.w);
            if (WRITE_OUT) {
                const float4 d = ldg_f4_force(paramD + co);
                const float a = 1.0f - om;
                float4 o;
                o.x = fmaf(u.x, d.x, a * z[i].x);
                o.y = fmaf(u.y, d.y, a * z[i].y);
                o.z = fmaf(u.z, d.z, a * z[i].z);
                o.w = fmaf(u.w, d.w, a * z[i].w);
                __stcs((float4*)(op + i * 128), o);
            }
        }
        xp += DIMN;
        if (WRITE_OUT) op += DIMN;
    }

    if (!WRITE_OUT) {
        float* s = g_S + (size_t)warp * DIMN + lane * 4;
#pragma unroll
        for (int i = 0; i < 8; i++) *(float4*)(s + i * 128) = z[i];
    }
}

__device__ __forceinline__ float om_of(const float* __restrict__ alphas, int ch) {
    float al = __ldg(alphas + (ch >> 7));
    return 1.0f - 1.0f / (1.0f + expf(-al));
}
__device__ __forceinline__ float pow8(float om) {
    float om2 = om * om, om4 = om2 * om2;
    return om4 * om4;                        // om^CHUNK (CHUNK==8)
}

// Phase A: per-(b,seg,ch) segment aggregate A = sum_j omC^(SEGLEN-1-j) * S[seg*SEGLEN+j].
__global__ void mhesa_carryA(const float* __restrict__ alphas)
{
    const int t = blockIdx.x * 256 + threadIdx.x;     // 0..65535
    const int ch = t & (DIMN - 1);
    const int rest = t >> 10;                          // b*NSEG + seg
    const float omC = pow8(om_of(alphas, ch));
    const size_t base = (size_t)rest * SEGLEN * DIMN + ch;   // (b*NCHUNK + seg*SEGLEN)*DIMN + ch
    float A = 0.f;
    for (int jj = 0; jj < SEGLEN; jj += 16) {
        float s[16];
#pragma unroll
        for (int k = 0; k < 16; k++) s[k] = g_S[base + (size_t)(jj + k) * DIMN];
#pragma unroll
        for (int k = 0; k < 16; k++) A = fmaf(omC, A, s[k]);
    }
    g_A[(size_t)rest * DIMN + ch] = A;
}

// Phase C: per-(b,seg,ch): fold aggregates of earlier segments into the segment
// entry carry, then write chunk entry carries for this segment.
__global__ void mhesa_carryC(const float* __restrict__ alphas)
{
    const int t = blockIdx.x * 256 + threadIdx.x;
    const int ch = t & (DIMN - 1);
    const int rest = t >> 10;
    const int seg = rest & (NSEG - 1);
    const int b = rest >> 4;
    const float omC = pow8(om_of(alphas, ch));
    // omSeg = omC^SEGLEN (SEGLEN==64): 6 squarings
    float omSeg = omC;
    omSeg = omSeg * omSeg; omSeg = omSeg * omSeg; omSeg = omSeg * omSeg;
    omSeg = omSeg * omSeg; omSeg = omSeg * omSeg; omSeg = omSeg * omSeg;

    float p = 0.f;
    const size_t abase = (size_t)b * NSEG * DIMN + ch;
    for (int s = 0; s < seg; s++)
        p = fmaf(omSeg, p, g_A[abase + (size_t)s * DIMN]);

    const size_t base = (size_t)rest * SEGLEN * DIMN + ch;
    for (int jj = 0; jj < SEGLEN; jj += 16) {
        float s[16];
#pragma unroll
        for (int k = 0; k < 16; k++) s[k] = g_S[base + (size_t)(jj + k) * DIMN];
#pragma unroll
        for (int k = 0; k < 16; k++) {
            g_P[base + (size_t)(jj + k) * DIMN] = p;
            p = fmaf(omC, p, s[k]);
        }
    }
}

extern "C" void kernel_launch(void* const* d_in, const int* in_sizes, int n_in,
                              void* d_out, int out_size)
{
    const float* x      = (const float*)d_in[0];
    const float* gamma  = (const float*)d_in[1];
    const float* beta   = (const float*)d_in[2];
    const float* alphas = (const float*)d_in[3];
    const float* paramD = (const float*)d_in[4];
    float* out = (float*)d_out;

    mhesa_scan<false><<<NBLOCKS, 256>>>(x, gamma, beta, alphas, paramD, out);
    mhesa_carryA<<<(BATCH * NSEG * DIMN) / 256, 256>>>(alphas);
    mhesa_carryC<<<(BATCH * NSEG * DIMN) / 256, 256>>>(alphas);
    mhesa_scan<true><<<NBLOCKS, 256>>>(x, gamma, beta, alphas, paramD, out);
}